// round 1
// baseline (speedup 1.0000x reference)
#include <cuda_runtime.h>
#include <math.h>

#define B_ 4
#define L_ 256
#define D_ 512
#define H_ 8
#define DK_ 64

// Scratch (allocation-free rule: __device__ globals)
__device__ float g_qh[B_*H_*L_*DK_];
__device__ float g_kh[B_*H_*L_*DK_];
__device__ float g_vh[B_*H_*L_*DK_];
__device__ float g_ctx[B_*L_*D_];

__device__ __forceinline__ float tanh_fast(float x) {
    float y;
    asm("tanh.approx.f32 %0, %1;" : "=f"(y) : "f"(x));
    return y;
}

// ---------------------------------------------------------------------------
// Fused QKV projection: Y = X @ W + b, written in head-split (B,H,L,DK) layout.
// grid (BL/64, D/64, 3), block 256. z selects q/k/v.
// ---------------------------------------------------------------------------
__global__ __launch_bounds__(256) void qkv_proj_kernel(
    const float* __restrict__ q, const float* __restrict__ k, const float* __restrict__ v,
    const float* __restrict__ Wq, const float* __restrict__ bq,
    const float* __restrict__ Wk, const float* __restrict__ bk,
    const float* __restrict__ Wv, const float* __restrict__ bv)
{
    __shared__ __align__(16) float Xs[16][68];   // [k][m]
    __shared__ __align__(16) float Ws[16][68];   // [k][n]

    int z = blockIdx.z;
    const float* X    = (z == 0) ? q  : (z == 1 ? k  : v);
    const float* W    = (z == 0) ? Wq : (z == 1 ? Wk : Wv);
    const float* bias = (z == 0) ? bq : (z == 1 ? bk : bv);
    float* out        = (z == 0) ? g_qh : (z == 1 ? g_kh : g_vh);

    int tid = threadIdx.x;
    int tx = tid & 15, ty = tid >> 4;
    int m0 = blockIdx.x * 64;
    int n0 = blockIdx.y * 64;

    float acc[4][4] = {};

    for (int k0 = 0; k0 < D_; k0 += 16) {
        // Load X tile (64 rows x 16 cols), transposed into Xs[k][m]
        {
            int mm = tid >> 2;
            int kk = (tid & 3) * 4;
            float4 xv = *(const float4*)&X[(size_t)(m0 + mm) * D_ + k0 + kk];
            Xs[kk + 0][mm] = xv.x;
            Xs[kk + 1][mm] = xv.y;
            Xs[kk + 2][mm] = xv.z;
            Xs[kk + 3][mm] = xv.w;
        }
        // Load W tile (16 rows x 64 cols)
        {
            int kw = tid >> 4;
            int nn = (tid & 15) * 4;
            *(float4*)&Ws[kw][nn] = *(const float4*)&W[(size_t)(k0 + kw) * D_ + n0 + nn];
        }
        __syncthreads();
        #pragma unroll
        for (int kk = 0; kk < 16; kk++) {
            float4 a4 = *(const float4*)&Xs[kk][ty * 4];
            float4 b4 = *(const float4*)&Ws[kk][tx * 4];
            acc[0][0] += a4.x * b4.x; acc[0][1] += a4.x * b4.y; acc[0][2] += a4.x * b4.z; acc[0][3] += a4.x * b4.w;
            acc[1][0] += a4.y * b4.x; acc[1][1] += a4.y * b4.y; acc[1][2] += a4.y * b4.z; acc[1][3] += a4.y * b4.w;
            acc[2][0] += a4.z * b4.x; acc[2][1] += a4.z * b4.y; acc[2][2] += a4.z * b4.z; acc[2][3] += a4.z * b4.w;
            acc[3][0] += a4.w * b4.x; acc[3][1] += a4.w * b4.y; acc[3][2] += a4.w * b4.z; acc[3][3] += a4.w * b4.w;
        }
        __syncthreads();
    }

    float4 bv4 = *(const float4*)&bias[n0 + tx * 4];
    int h = n0 >> 6;  // n0 is a multiple of 64, so whole tile is one head
    #pragma unroll
    for (int a = 0; a < 4; a++) {
        int m = m0 + ty * 4 + a;       // global token index
        int bI = m >> 8;               // batch
        int i  = m & 255;              // seq pos
        float4 r;
        r.x = acc[a][0] + bv4.x;
        r.y = acc[a][1] + bv4.y;
        r.z = acc[a][2] + bv4.z;
        r.w = acc[a][3] + bv4.w;
        *(float4*)&out[(size_t)((bI * H_ + h) * L_ + i) * DK_ + tx * 4] = r;
    }
}

// ---------------------------------------------------------------------------
// Output projection: d_out = g_ctx @ W0 + b0 (flat row-major). grid (16,8).
// ---------------------------------------------------------------------------
__global__ __launch_bounds__(256) void out_proj_kernel(
    const float* __restrict__ W, const float* __restrict__ bias,
    float* __restrict__ Y)
{
    __shared__ __align__(16) float Xs[16][68];
    __shared__ __align__(16) float Ws[16][68];

    const float* X = g_ctx;
    int tid = threadIdx.x;
    int tx = tid & 15, ty = tid >> 4;
    int m0 = blockIdx.x * 64;
    int n0 = blockIdx.y * 64;

    float acc[4][4] = {};

    for (int k0 = 0; k0 < D_; k0 += 16) {
        {
            int mm = tid >> 2;
            int kk = (tid & 3) * 4;
            float4 xv = *(const float4*)&X[(size_t)(m0 + mm) * D_ + k0 + kk];
            Xs[kk + 0][mm] = xv.x;
            Xs[kk + 1][mm] = xv.y;
            Xs[kk + 2][mm] = xv.z;
            Xs[kk + 3][mm] = xv.w;
        }
        {
            int kw = tid >> 4;
            int nn = (tid & 15) * 4;
            *(float4*)&Ws[kw][nn] = *(const float4*)&W[(size_t)(k0 + kw) * D_ + n0 + nn];
        }
        __syncthreads();
        #pragma unroll
        for (int kk = 0; kk < 16; kk++) {
            float4 a4 = *(const float4*)&Xs[kk][ty * 4];
            float4 b4 = *(const float4*)&Ws[kk][tx * 4];
            acc[0][0] += a4.x * b4.x; acc[0][1] += a4.x * b4.y; acc[0][2] += a4.x * b4.z; acc[0][3] += a4.x * b4.w;
            acc[1][0] += a4.y * b4.x; acc[1][1] += a4.y * b4.y; acc[1][2] += a4.y * b4.z; acc[1][3] += a4.y * b4.w;
            acc[2][0] += a4.z * b4.x; acc[2][1] += a4.z * b4.y; acc[2][2] += a4.z * b4.z; acc[2][3] += a4.z * b4.w;
            acc[3][0] += a4.w * b4.x; acc[3][1] += a4.w * b4.y; acc[3][2] += a4.w * b4.z; acc[3][3] += a4.w * b4.w;
        }
        __syncthreads();
    }

    float4 bv4 = *(const float4*)&bias[n0 + tx * 4];
    #pragma unroll
    for (int a = 0; a < 4; a++) {
        int m = m0 + ty * 4 + a;
        float4 r;
        r.x = acc[a][0] + bv4.x;
        r.y = acc[a][1] + bv4.y;
        r.z = acc[a][2] + bv4.z;
        r.w = acc[a][3] + bv4.w;
        *(float4*)&Y[(size_t)m * D_ + n0 + tx * 4] = r;
    }
}

// ---------------------------------------------------------------------------
// Fused Bahdanau attention. One CTA per (b, h, 64-row i-block): grid (4, 32).
// SMEM: Qs[d][i] (64x68), Ks[d][j] (64x68), Vs[j][dk] (256x64),
//       S[i][j] (64x260), vps[64], rinv[64]  => 167424 bytes.
// ---------------------------------------------------------------------------
#define ATTN_SMEM_FLOATS (64*68 + 64*68 + 256*64 + 64*260 + 64 + 64)
#define ATTN_SMEM_BYTES  (ATTN_SMEM_FLOATS * 4)

__global__ __launch_bounds__(256) void attn_kernel(
    const int* __restrict__ mask, const float* __restrict__ vp)
{
    extern __shared__ __align__(16) float sm[];
    float* Qs   = sm;                  // 64*68
    float* Ks   = Qs + 64 * 68;        // 64*68
    float* Vs   = Ks + 64 * 68;        // 256*64
    float* S    = Vs + 256 * 64;       // 64*260
    float* vps  = S + 64 * 260;        // 64
    float* rinv = vps + 64;            // 64

    int tid = threadIdx.x;
    int bh = blockIdx.y;
    int b = bh >> 3;
    int h = bh & 7;
    int i0 = blockIdx.x * 64;

    const float* qh  = g_qh + (size_t)(bh * L_ + i0) * DK_;
    const float* khp = g_kh + (size_t)bh * L_ * DK_;
    const float* vhp = g_vh + (size_t)bh * L_ * DK_;

    if (tid < 64) vps[tid] = vp[h * DK_ + tid];

    // Load Q tile transposed: Qs[d][i]
    {
        int i  = tid >> 2;
        int d0 = (tid & 3) * 16;
        #pragma unroll
        for (int u = 0; u < 4; u++) {
            float4 t4 = *(const float4*)&qh[(size_t)i * DK_ + d0 + u * 4];
            Qs[(d0 + u * 4 + 0) * 68 + i] = t4.x;
            Qs[(d0 + u * 4 + 1) * 68 + i] = t4.y;
            Qs[(d0 + u * 4 + 2) * 68 + i] = t4.z;
            Qs[(d0 + u * 4 + 3) * 68 + i] = t4.w;
        }
    }
    // Load full V (256 x 64), row-major
    {
        const float4* src = (const float4*)vhp;
        float4* dst = (float4*)Vs;
        #pragma unroll
        for (int t = tid; t < (L_ * DK_) / 4; t += 256) dst[t] = src[t];
    }

    int ti = tid & 15;   // i-tile: rows ti*4 .. ti*4+3
    int tj = tid >> 4;   // j-tile: cols tj*4 .. tj*4+3

    // -------- Score computation: S[i][j] = sum_d vp[d]*tanh(q[i][d]+k[j][d])
    for (int jb = 0; jb < 4; jb++) {
        __syncthreads();  // previous tile consumers done (also covers Q/V/vps loads)
        {
            int j  = tid >> 2;
            int d0 = (tid & 3) * 16;
            const float* kr = khp + (size_t)(jb * 64 + j) * DK_;
            #pragma unroll
            for (int u = 0; u < 4; u++) {
                float4 t4 = *(const float4*)&kr[d0 + u * 4];
                Ks[(d0 + u * 4 + 0) * 68 + j] = t4.x;
                Ks[(d0 + u * 4 + 1) * 68 + j] = t4.y;
                Ks[(d0 + u * 4 + 2) * 68 + j] = t4.z;
                Ks[(d0 + u * 4 + 3) * 68 + j] = t4.w;
            }
        }
        __syncthreads();

        float acc[4][4] = {};
        #pragma unroll 2
        for (int d = 0; d < 64; d++) {
            float w = vps[d];
            float4 qv = *(const float4*)&Qs[d * 68 + ti * 4];
            float4 kv = *(const float4*)&Ks[d * 68 + tj * 4];
            float qa[4] = {qv.x, qv.y, qv.z, qv.w};
            float kb[4] = {kv.x, kv.y, kv.z, kv.w};
            #pragma unroll
            for (int a = 0; a < 4; a++)
                #pragma unroll
                for (int c = 0; c < 4; c++)
                    acc[a][c] += w * tanh_fast(qa[a] + kb[c]);
        }
        #pragma unroll
        for (int a = 0; a < 4; a++)
            #pragma unroll
            for (int c = 0; c < 4; c++)
                S[(ti * 4 + a) * 260 + jb * 64 + tj * 4 + c] = acc[a][c];
    }
    __syncthreads();

    // -------- Masked softmax per row (warp-per-row, 8 rows per warp)
    {
        int warp = tid >> 5, lane = tid & 31;
        for (int r = 0; r < 8; r++) {
            int row = warp * 8 + r;
            const int* mrow = mask + ((size_t)b * L_ + i0 + row) * L_;
            float vals[8];
            float mmax = -3.4e38f;
            #pragma unroll
            for (int c8 = 0; c8 < 8; c8++) {
                int c = c8 * 32 + lane;
                float s = S[row * 260 + c];
                if (mrow[c] == 0) s = -1.0e9f;
                vals[c8] = s;
                mmax = fmaxf(mmax, s);
            }
            #pragma unroll
            for (int off = 16; off > 0; off >>= 1)
                mmax = fmaxf(mmax, __shfl_xor_sync(0xFFFFFFFFu, mmax, off));
            float sum = 0.0f;
            #pragma unroll
            for (int c8 = 0; c8 < 8; c8++) {
                float e = __expf(vals[c8] - mmax);
                S[row * 260 + c8 * 32 + lane] = e;
                sum += e;
            }
            #pragma unroll
            for (int off = 16; off > 0; off >>= 1)
                sum += __shfl_xor_sync(0xFFFFFFFFu, sum, off);
            if (lane == 0) rinv[row] = 1.0f / sum;
        }
    }
    __syncthreads();

    // -------- PV: out[i][dk] = rinv[i] * sum_j S[i][j] * V[j][dk]
    {
        int i   = tid >> 2;
        int dk0 = (tid & 3) * 16;
        float o[16] = {};
        #pragma unroll 4
        for (int j = 0; j < L_; j++) {
            float p = S[i * 260 + j];
            const float4* vr = (const float4*)&Vs[j * DK_ + dk0];
            float4 v0 = vr[0], v1 = vr[1], v2 = vr[2], v3 = vr[3];
            o[0]  += p * v0.x; o[1]  += p * v0.y; o[2]  += p * v0.z; o[3]  += p * v0.w;
            o[4]  += p * v1.x; o[5]  += p * v1.y; o[6]  += p * v1.z; o[7]  += p * v1.w;
            o[8]  += p * v2.x; o[9]  += p * v2.y; o[10] += p * v2.z; o[11] += p * v2.w;
            o[12] += p * v3.x; o[13] += p * v3.y; o[14] += p * v3.z; o[15] += p * v3.w;
        }
        float inv = rinv[i];
        float* dst = &g_ctx[((size_t)b * L_ + i0 + i) * D_ + h * DK_ + dk0];
        #pragma unroll
        for (int u = 0; u < 4; u++) {
            float4 r;
            r.x = o[u * 4 + 0] * inv;
            r.y = o[u * 4 + 1] * inv;
            r.z = o[u * 4 + 2] * inv;
            r.w = o[u * 4 + 3] * inv;
            *(float4*)&dst[u * 4] = r;
        }
    }
}

// ---------------------------------------------------------------------------
extern "C" void kernel_launch(void* const* d_in, const int* in_sizes, int n_in,
                              void* d_out, int out_size)
{
    const float* q    = (const float*)d_in[0];
    const float* k    = (const float*)d_in[1];
    const float* v    = (const float*)d_in[2];
    const int*   mask = (const int*)  d_in[3];
    const float* Wq   = (const float*)d_in[4];
    const float* bq   = (const float*)d_in[5];
    const float* Wk   = (const float*)d_in[6];
    const float* bk   = (const float*)d_in[7];
    const float* Wv   = (const float*)d_in[8];
    const float* bv   = (const float*)d_in[9];
    const float* vp   = (const float*)d_in[10];
    const float* W0   = (const float*)d_in[11];
    const float* b0   = (const float*)d_in[12];
    float* out = (float*)d_out;

    static bool attr_set = false;
    if (!attr_set) {
        cudaFuncSetAttribute(attn_kernel,
                             cudaFuncAttributeMaxDynamicSharedMemorySize,
                             ATTN_SMEM_BYTES);
        attr_set = true;
    }

    qkv_proj_kernel<<<dim3(16, 8, 3), 256>>>(q, k, v, Wq, bq, Wk, bk, Wv, bv);
    attn_kernel<<<dim3(4, 32), 256, ATTN_SMEM_BYTES>>>(mask, vp);
    out_proj_kernel<<<dim3(16, 8), 256>>>(W0, b0, out);
}

// round 4
// speedup vs baseline: 1.0154x; 1.0154x over previous
#include <cuda_runtime.h>
#include <cstdint>
#include <math.h>

#define B_ 4
#define L_ 256
#define D_ 512
#define H_ 8
#define DK_ 64

// Scratch (allocation-free rule: __device__ globals)
__device__ float g_qh[B_*H_*L_*DK_];
__device__ float g_kh[B_*H_*L_*DK_];
__device__ float g_vh[B_*H_*L_*DK_];
__device__ float g_ctx[B_*L_*D_];

__device__ __forceinline__ float tanh_fast(float x) {
    float y;
    asm("tanh.approx.f32 %0, %1;" : "=f"(y) : "f"(x));
    return y;
}

__device__ __forceinline__ float to_tf32f(float x) {
    uint32_t u;
    asm("cvt.rna.tf32.f32 %0, %1;" : "=r"(u) : "f"(x));
    return __uint_as_float(u);
}

// m16n8k8 tf32 MMA (sm_80+ PTX, works on plain compute_103 target)
__device__ __forceinline__ void mma_tf32(float* c, const uint32_t* a, const uint32_t* b) {
    asm volatile(
        "mma.sync.aligned.m16n8k8.row.col.f32.tf32.tf32.f32 "
        "{%0,%1,%2,%3}, {%4,%5,%6,%7}, {%8,%9}, {%0,%1,%2,%3};"
        : "+f"(c[0]), "+f"(c[1]), "+f"(c[2]), "+f"(c[3])
        : "r"(a[0]), "r"(a[1]), "r"(a[2]), "r"(a[3]),
          "r"(b[0]), "r"(b[1]));
}

// ===========================================================================
// 3xTF32 tensor-core GEMM core.
// C[m0:m0+MT, n0:n0+64] = X @ W + bias   (X: [1024,512], W: [512,512] row-major)
// K staged 32 per iter; A smem [m][k] stride 36 (conflict-free frag LDS),
// B smem [k][n] stride 68 (natural layout, vectorized STS).
// 8 warps arranged WM x WN; warp tile (MT/WM) x (64/WN).
// ===========================================================================
#define A_STRIDE 36
#define B_STRIDE 68

template<int MT, int WM, int WN, bool HEADSPLIT>
__device__ __forceinline__ void gemm3x_core(
    const float* __restrict__ X, const float* __restrict__ W,
    const float* __restrict__ bias, float* __restrict__ Y)
{
    extern __shared__ __align__(16) float smf[];
    constexpr int A_FLOATS = MT * A_STRIDE;
    constexpr int B_FLOATS = 32 * B_STRIDE;
    float* As_hi = smf;
    float* As_lo = As_hi + A_FLOATS;
    float* Bs_hi = As_lo + A_FLOATS;
    float* Bs_lo = Bs_hi + B_FLOATS;

    constexpr int MTILES = (MT / WM) / 16;
    constexpr int NTILES = (64 / WN) / 8;

    const int tid = threadIdx.x;
    const int wid = tid >> 5, lane = tid & 31;
    const int g = lane >> 2, t4 = lane & 3;
    const int warp_m = (wid % WM) * (MT / WM);
    const int warp_n = (wid / WM) * (64 / WN);
    const int m0 = blockIdx.x * MT;
    const int n0 = blockIdx.y * 64;

    float acc[MTILES][NTILES][4];
    #pragma unroll
    for (int i = 0; i < MTILES; i++)
        #pragma unroll
        for (int j = 0; j < NTILES; j++)
            #pragma unroll
            for (int c = 0; c < 4; c++) acc[i][j][c] = 0.0f;

    constexpr int TPR = 256 / MT;      // threads per A row
    constexpr int KPT = 32 / TPR;      // k floats per thread
    const int am = tid / TPR;
    const int aks = (tid % TPR) * KPT;
    const int bk = tid >> 3;
    const int bn = (tid & 7) * 8;

    for (int s = 0; s < 16; s++) {
        const int k0 = s * 32;
        // ---- A tile: X[m0+am][k0+aks .. +KPT] -> hi/lo ----
        {
            const float* src = X + (size_t)(m0 + am) * D_ + k0 + aks;
            #pragma unroll
            for (int u = 0; u < KPT / 4; u++) {
                float4 xv = *(const float4*)(src + u * 4);
                float4 hi, lo;
                hi.x = to_tf32f(xv.x); lo.x = to_tf32f(xv.x - hi.x);
                hi.y = to_tf32f(xv.y); lo.y = to_tf32f(xv.y - hi.y);
                hi.z = to_tf32f(xv.z); lo.z = to_tf32f(xv.z - hi.z);
                hi.w = to_tf32f(xv.w); lo.w = to_tf32f(xv.w - hi.w);
                *(float4*)&As_hi[am * A_STRIDE + aks + u * 4] = hi;
                *(float4*)&As_lo[am * A_STRIDE + aks + u * 4] = lo;
            }
        }
        // ---- B tile: W[k0+bk][n0+bn .. +8] -> hi/lo (natural [k][n]) ----
        {
            const float* src = W + (size_t)(k0 + bk) * D_ + n0 + bn;
            #pragma unroll
            for (int u = 0; u < 2; u++) {
                float4 wv = *(const float4*)(src + u * 4);
                float4 hi, lo;
                hi.x = to_tf32f(wv.x); lo.x = to_tf32f(wv.x - hi.x);
                hi.y = to_tf32f(wv.y); lo.y = to_tf32f(wv.y - hi.y);
                hi.z = to_tf32f(wv.z); lo.z = to_tf32f(wv.z - hi.z);
                hi.w = to_tf32f(wv.w); lo.w = to_tf32f(wv.w - hi.w);
                *(float4*)&Bs_hi[bk * B_STRIDE + bn + u * 4] = hi;
                *(float4*)&Bs_lo[bk * B_STRIDE + bn + u * 4] = lo;
            }
        }
        __syncthreads();

        #pragma unroll
        for (int kk = 0; kk < 4; kk++) {
            const int kb = kk * 8;
            uint32_t ahi[MTILES][4], alo[MTILES][4];
            #pragma unroll
            for (int i = 0; i < MTILES; i++) {
                int rm = warp_m + i * 16;
                ahi[i][0] = __float_as_uint(As_hi[(rm + g)     * A_STRIDE + kb + t4]);
                ahi[i][1] = __float_as_uint(As_hi[(rm + 8 + g) * A_STRIDE + kb + t4]);
                ahi[i][2] = __float_as_uint(As_hi[(rm + g)     * A_STRIDE + kb + t4 + 4]);
                ahi[i][3] = __float_as_uint(As_hi[(rm + 8 + g) * A_STRIDE + kb + t4 + 4]);
                alo[i][0] = __float_as_uint(As_lo[(rm + g)     * A_STRIDE + kb + t4]);
                alo[i][1] = __float_as_uint(As_lo[(rm + 8 + g) * A_STRIDE + kb + t4]);
                alo[i][2] = __float_as_uint(As_lo[(rm + g)     * A_STRIDE + kb + t4 + 4]);
                alo[i][3] = __float_as_uint(As_lo[(rm + 8 + g) * A_STRIDE + kb + t4 + 4]);
            }
            uint32_t bhi[NTILES][2], blo[NTILES][2];
            #pragma unroll
            for (int j = 0; j < NTILES; j++) {
                int cn = warp_n + j * 8 + g;
                bhi[j][0] = __float_as_uint(Bs_hi[(kb + t4)     * B_STRIDE + cn]);
                bhi[j][1] = __float_as_uint(Bs_hi[(kb + t4 + 4) * B_STRIDE + cn]);
                blo[j][0] = __float_as_uint(Bs_lo[(kb + t4)     * B_STRIDE + cn]);
                blo[j][1] = __float_as_uint(Bs_lo[(kb + t4 + 4) * B_STRIDE + cn]);
            }
            #pragma unroll
            for (int i = 0; i < MTILES; i++)
                #pragma unroll
                for (int j = 0; j < NTILES; j++) {
                    mma_tf32(acc[i][j], ahi[i], bhi[j]);
                    mma_tf32(acc[i][j], ahi[i], blo[j]);
                    mma_tf32(acc[i][j], alo[i], bhi[j]);
                }
        }
        __syncthreads();
    }

    // ---- Epilogue: bias + store (c0,c1 -> row g; c2,c3 -> row g+8) ----
    #pragma unroll
    for (int i = 0; i < MTILES; i++) {
        #pragma unroll
        for (int j = 0; j < NTILES; j++) {
            int col_loc = warp_n + j * 8 + 2 * t4;     // 0..63 within tile
            int cng = n0 + col_loc;                    // global column
            float b0 = bias[cng], b1 = bias[cng + 1];
            int r0 = m0 + warp_m + i * 16 + g;
            int r1 = r0 + 8;
            float2 v0 = make_float2(acc[i][j][0] + b0, acc[i][j][1] + b1);
            float2 v1 = make_float2(acc[i][j][2] + b0, acc[i][j][3] + b1);
            if (HEADSPLIT) {
                int h = blockIdx.y;  // 64-wide N tile == one head
                float* d0 = Y + ((size_t)((r0 >> 8) * H_ + h) * L_ + (r0 & 255)) * DK_ + col_loc;
                float* d1 = Y + ((size_t)((r1 >> 8) * H_ + h) * L_ + (r1 & 255)) * DK_ + col_loc;
                *(float2*)d0 = v0;
                *(float2*)d1 = v1;
            } else {
                *(float2*)(Y + (size_t)r0 * D_ + cng) = v0;
                *(float2*)(Y + (size_t)r1 * D_ + cng) = v1;
            }
        }
    }
}

constexpr int gemm_smem_bytes(int mt) {
    return (2 * mt * A_STRIDE + 2 * 32 * B_STRIDE) * 4;
}

// QKV: grid (8, 8, 3), MT=128, warps 4x2, head-split output
__global__ __launch_bounds__(256) void qkv_mma_kernel(
    const float* __restrict__ q, const float* __restrict__ k, const float* __restrict__ v,
    const float* __restrict__ Wq, const float* __restrict__ bq,
    const float* __restrict__ Wk, const float* __restrict__ bk,
    const float* __restrict__ Wv, const float* __restrict__ bv)
{
    int z = blockIdx.z;
    const float* X    = (z == 0) ? q  : (z == 1 ? k  : v);
    const float* W    = (z == 0) ? Wq : (z == 1 ? Wk : Wv);
    const float* bias = (z == 0) ? bq : (z == 1 ? bk : bv);
    float* out        = (z == 0) ? g_qh : (z == 1 ? g_kh : g_vh);
    gemm3x_core<128, 4, 2, true>(X, W, bias, out);
}

// Output projection: grid (16, 8), MT=64, warps 2x4, flat output
__global__ __launch_bounds__(256) void out_mma_kernel(
    const float* __restrict__ W, const float* __restrict__ bias, float* __restrict__ Y)
{
    gemm3x_core<64, 2, 4, false>(g_ctx, W, bias, Y);
}

// ===========================================================================
// Fused Bahdanau attention (unchanged). One CTA per (b,h,64-row block).
// ===========================================================================
#define ATTN_SMEM_FLOATS (64*68 + 64*68 + 256*64 + 64*260 + 64 + 64)
#define ATTN_SMEM_BYTES  (ATTN_SMEM_FLOATS * 4)

__global__ __launch_bounds__(256) void attn_kernel(
    const int* __restrict__ mask, const float* __restrict__ vp)
{
    extern __shared__ __align__(16) float sm[];
    float* Qs   = sm;
    float* Ks   = Qs + 64 * 68;
    float* Vs   = Ks + 64 * 68;
    float* S    = Vs + 256 * 64;
    float* vps  = S + 64 * 260;
    float* rinv = vps + 64;

    int tid = threadIdx.x;
    int bh = blockIdx.y;
    int b = bh >> 3;
    int h = bh & 7;
    int i0 = blockIdx.x * 64;

    const float* qh  = g_qh + (size_t)(bh * L_ + i0) * DK_;
    const float* khp = g_kh + (size_t)bh * L_ * DK_;
    const float* vhp = g_vh + (size_t)bh * L_ * DK_;

    if (tid < 64) vps[tid] = vp[h * DK_ + tid];

    {
        int i  = tid >> 2;
        int d0 = (tid & 3) * 16;
        #pragma unroll
        for (int u = 0; u < 4; u++) {
            float4 t4 = *(const float4*)&qh[(size_t)i * DK_ + d0 + u * 4];
            Qs[(d0 + u * 4 + 0) * 68 + i] = t4.x;
            Qs[(d0 + u * 4 + 1) * 68 + i] = t4.y;
            Qs[(d0 + u * 4 + 2) * 68 + i] = t4.z;
            Qs[(d0 + u * 4 + 3) * 68 + i] = t4.w;
        }
    }
    {
        const float4* src = (const float4*)vhp;
        float4* dst = (float4*)Vs;
        #pragma unroll
        for (int t = tid; t < (L_ * DK_) / 4; t += 256) dst[t] = src[t];
    }

    int ti = tid & 15;
    int tj = tid >> 4;

    for (int jb = 0; jb < 4; jb++) {
        __syncthreads();
        {
            int j  = tid >> 2;
            int d0 = (tid & 3) * 16;
            const float* kr = khp + (size_t)(jb * 64 + j) * DK_;
            #pragma unroll
            for (int u = 0; u < 4; u++) {
                float4 t4 = *(const float4*)&kr[d0 + u * 4];
                Ks[(d0 + u * 4 + 0) * 68 + j] = t4.x;
                Ks[(d0 + u * 4 + 1) * 68 + j] = t4.y;
                Ks[(d0 + u * 4 + 2) * 68 + j] = t4.z;
                Ks[(d0 + u * 4 + 3) * 68 + j] = t4.w;
            }
        }
        __syncthreads();

        float acc[4][4] = {};
        #pragma unroll 2
        for (int d = 0; d < 64; d++) {
            float w = vps[d];
            float4 qv = *(const float4*)&Qs[d * 68 + ti * 4];
            float4 kv = *(const float4*)&Ks[d * 68 + tj * 4];
            float qa[4] = {qv.x, qv.y, qv.z, qv.w};
            float kb[4] = {kv.x, kv.y, kv.z, kv.w};
            #pragma unroll
            for (int a = 0; a < 4; a++)
                #pragma unroll
                for (int c = 0; c < 4; c++)
                    acc[a][c] += w * tanh_fast(qa[a] + kb[c]);
        }
        #pragma unroll
        for (int a = 0; a < 4; a++)
            #pragma unroll
            for (int c = 0; c < 4; c++)
                S[(ti * 4 + a) * 260 + jb * 64 + tj * 4 + c] = acc[a][c];
    }
    __syncthreads();

    {
        int warp = tid >> 5, lane = tid & 31;
        for (int r = 0; r < 8; r++) {
            int row = warp * 8 + r;
            const int* mrow = mask + ((size_t)b * L_ + i0 + row) * L_;
            float vals[8];
            float mmax = -3.4e38f;
            #pragma unroll
            for (int c8 = 0; c8 < 8; c8++) {
                int c = c8 * 32 + lane;
                float s = S[row * 260 + c];
                if (mrow[c] == 0) s = -1.0e9f;
                vals[c8] = s;
                mmax = fmaxf(mmax, s);
            }
            #pragma unroll
            for (int off = 16; off > 0; off >>= 1)
                mmax = fmaxf(mmax, __shfl_xor_sync(0xFFFFFFFFu, mmax, off));
            float sum = 0.0f;
            #pragma unroll
            for (int c8 = 0; c8 < 8; c8++) {
                float e = __expf(vals[c8] - mmax);
                S[row * 260 + c8 * 32 + lane] = e;
                sum += e;
            }
            #pragma unroll
            for (int off = 16; off > 0; off >>= 1)
                sum += __shfl_xor_sync(0xFFFFFFFFu, sum, off);
            if (lane == 0) rinv[row] = 1.0f / sum;
        }
    }
    __syncthreads();

    {
        int i   = tid >> 2;
        int dk0 = (tid & 3) * 16;
        float o[16] = {};
        #pragma unroll 4
        for (int j = 0; j < L_; j++) {
            float p = S[i * 260 + j];
            const float4* vr = (const float4*)&Vs[j * DK_ + dk0];
            float4 v0 = vr[0], v1 = vr[1], v2 = vr[2], v3 = vr[3];
            o[0]  += p * v0.x; o[1]  += p * v0.y; o[2]  += p * v0.z; o[3]  += p * v0.w;
            o[4]  += p * v1.x; o[5]  += p * v1.y; o[6]  += p * v1.z; o[7]  += p * v1.w;
            o[8]  += p * v2.x; o[9]  += p * v2.y; o[10] += p * v2.z; o[11] += p * v2.w;
            o[12] += p * v3.x; o[13] += p * v3.y; o[14] += p * v3.z; o[15] += p * v3.w;
        }
        float inv = rinv[i];
        float* dst = &g_ctx[((size_t)b * L_ + i0 + i) * D_ + h * DK_ + dk0];
        #pragma unroll
        for (int u = 0; u < 4; u++) {
            float4 r;
            r.x = o[u * 4 + 0] * inv;
            r.y = o[u * 4 + 1] * inv;
            r.z = o[u * 4 + 2] * inv;
            r.w = o[u * 4 + 3] * inv;
            *(float4*)&dst[u * 4] = r;
        }
    }
}

// ===========================================================================
extern "C" void kernel_launch(void* const* d_in, const int* in_sizes, int n_in,
                              void* d_out, int out_size)
{
    const float* q    = (const float*)d_in[0];
    const float* k    = (const float*)d_in[1];
    const float* v    = (const float*)d_in[2];
    const int*   mask = (const int*)  d_in[3];
    const float* Wq   = (const float*)d_in[4];
    const float* bq   = (const float*)d_in[5];
    const float* Wk   = (const float*)d_in[6];
    const float* bk   = (const float*)d_in[7];
    const float* Wv   = (const float*)d_in[8];
    const float* bv   = (const float*)d_in[9];
    const float* vp   = (const float*)d_in[10];
    const float* W0   = (const float*)d_in[11];
    const float* b0   = (const float*)d_in[12];
    float* out = (float*)d_out;

    static bool attr_set = false;
    if (!attr_set) {
        cudaFuncSetAttribute(attn_kernel,
                             cudaFuncAttributeMaxDynamicSharedMemorySize, ATTN_SMEM_BYTES);
        cudaFuncSetAttribute(qkv_mma_kernel,
                             cudaFuncAttributeMaxDynamicSharedMemorySize, gemm_smem_bytes(128));
        cudaFuncSetAttribute(out_mma_kernel,
                             cudaFuncAttributeMaxDynamicSharedMemorySize, gemm_smem_bytes(64));
        attr_set = true;
    }

    qkv_mma_kernel<<<dim3(8, 8, 3), 256, gemm_smem_bytes(128)>>>(
        q, k, v, Wq, bq, Wk, bk, Wv, bv);
    attn_kernel<<<dim3(4, 32), 256, ATTN_SMEM_BYTES>>>(mask, vp);
    out_mma_kernel<<<dim3(16, 8), 256, gemm_smem_bytes(64)>>>(W0, b0, out);
}

// round 5
// speedup vs baseline: 1.0450x; 1.0291x over previous
#include <cuda_runtime.h>
#include <cstdint>
#include <math.h>

#define B_ 4
#define L_ 256
#define D_ 512
#define H_ 8
#define DK_ 64

// Scratch (allocation-free rule: __device__ globals)
__device__ float g_qh[B_*H_*L_*DK_];
__device__ float g_kh[B_*H_*L_*DK_];
__device__ float g_vh[B_*H_*L_*DK_];
__device__ float g_ctx[B_*L_*D_];

__device__ __forceinline__ float tanh_fast(float x) {
    float y;
    asm("tanh.approx.f32 %0, %1;" : "=f"(y) : "f"(x));
    return y;
}

__device__ __forceinline__ float to_tf32f(float x) {
    uint32_t u;
    asm("cvt.rna.tf32.f32 %0, %1;" : "=r"(u) : "f"(x));
    return __uint_as_float(u);
}

// m16n8k8 tf32 MMA (sm_80+ PTX, works on plain compute_103 target)
__device__ __forceinline__ void mma_tf32(float* c, const uint32_t* a, const uint32_t* b) {
    asm volatile(
        "mma.sync.aligned.m16n8k8.row.col.f32.tf32.tf32.f32 "
        "{%0,%1,%2,%3}, {%4,%5,%6,%7}, {%8,%9}, {%0,%1,%2,%3};"
        : "+f"(c[0]), "+f"(c[1]), "+f"(c[2]), "+f"(c[3])
        : "r"(a[0]), "r"(a[1]), "r"(a[2]), "r"(a[3]),
          "r"(b[0]), "r"(b[1]));
}

// ===========================================================================
// 3xTF32 tensor-core GEMM, software-pipelined:
//   - register prefetch of stage s+1 LDG under stage-s MMAs
//   - double-buffered hi/lo SMEM, ONE __syncthreads per K-stage
// C[m0:m0+MT, n0:n0+64] = X @ W + bias  (X: [1024,512], W: [512,512] row-major)
// ===========================================================================
#define A_STRIDE 36
#define B_STRIDE 68

template<int MT, int WM, int WN, bool HEADSPLIT>
__device__ __forceinline__ void gemm3x_core(
    const float* __restrict__ X, const float* __restrict__ W,
    const float* __restrict__ bias, float* __restrict__ Y)
{
    extern __shared__ __align__(16) float smf[];
    constexpr int A_FLOATS = MT * A_STRIDE;
    constexpr int B_FLOATS = 32 * B_STRIDE;
    constexpr int BUF_FLOATS = 2 * A_FLOATS + 2 * B_FLOATS;

    constexpr int MTILES = (MT / WM) / 16;
    constexpr int NTILES = (64 / WN) / 8;
    constexpr int TPR = 256 / MT;      // threads per A row
    constexpr int KPT = 32 / TPR;      // k floats per thread (16 or 8)
    constexpr int APF = KPT / 4;       // float4 chunks of A per thread

    const int tid = threadIdx.x;
    const int wid = tid >> 5, lane = tid & 31;
    const int g = lane >> 2, t4 = lane & 3;
    const int warp_m = (wid % WM) * (MT / WM);
    const int warp_n = (wid / WM) * (64 / WN);
    const int m0 = blockIdx.x * MT;
    const int n0 = blockIdx.y * 64;

    const int am = tid / TPR;
    const int aks = (tid % TPR) * KPT;
    const int bk = tid >> 3;
    const int bn = (tid & 7) * 8;

    float acc[MTILES][NTILES][4];
    #pragma unroll
    for (int i = 0; i < MTILES; i++)
        #pragma unroll
        for (int j = 0; j < NTILES; j++)
            #pragma unroll
            for (int c = 0; c < 4; c++) acc[i][j][c] = 0.0f;

    const float* Abase = X + (size_t)(m0 + am) * D_ + aks;
    const float* Bbase = W + (size_t)bk * D_ + n0 + bn;

    float4 aP[APF], bP[2];

    // ---- prologue: LDG stage 0 into registers ----
    #pragma unroll
    for (int u = 0; u < APF; u++) aP[u] = *(const float4*)(Abase + u * 4);
    bP[0] = *(const float4*)(Bbase);
    bP[1] = *(const float4*)(Bbase + 4);

    for (int s = 0; s < 16; s++) {
        const int buf = s & 1;
        float* As_hi = smf + buf * BUF_FLOATS;
        float* As_lo = As_hi + A_FLOATS;
        float* Bs_hi = As_lo + A_FLOATS;
        float* Bs_lo = Bs_hi + B_FLOATS;

        // ---- STS: convert register-staged tiles to hi/lo in smem[buf] ----
        #pragma unroll
        for (int u = 0; u < APF; u++) {
            float4 xv = aP[u];
            float4 hi, lo;
            hi.x = to_tf32f(xv.x); lo.x = to_tf32f(xv.x - hi.x);
            hi.y = to_tf32f(xv.y); lo.y = to_tf32f(xv.y - hi.y);
            hi.z = to_tf32f(xv.z); lo.z = to_tf32f(xv.z - hi.z);
            hi.w = to_tf32f(xv.w); lo.w = to_tf32f(xv.w - hi.w);
            *(float4*)&As_hi[am * A_STRIDE + aks + u * 4] = hi;
            *(float4*)&As_lo[am * A_STRIDE + aks + u * 4] = lo;
        }
        #pragma unroll
        for (int u = 0; u < 2; u++) {
            float4 wv = bP[u];
            float4 hi, lo;
            hi.x = to_tf32f(wv.x); lo.x = to_tf32f(wv.x - hi.x);
            hi.y = to_tf32f(wv.y); lo.y = to_tf32f(wv.y - hi.y);
            hi.z = to_tf32f(wv.z); lo.z = to_tf32f(wv.z - hi.z);
            hi.w = to_tf32f(wv.w); lo.w = to_tf32f(wv.w - hi.w);
            *(float4*)&Bs_hi[bk * B_STRIDE + bn + u * 4] = hi;
            *(float4*)&Bs_lo[bk * B_STRIDE + bn + u * 4] = lo;
        }
        __syncthreads();

        // ---- prefetch stage s+1 (latency hidden under MMAs below) ----
        if (s < 15) {
            const float* an = Abase + (s + 1) * 32;
            const float* bnx = Bbase + (size_t)(s + 1) * 32 * D_;
            #pragma unroll
            for (int u = 0; u < APF; u++) aP[u] = *(const float4*)(an + u * 4);
            bP[0] = *(const float4*)(bnx);
            bP[1] = *(const float4*)(bnx + 4);
        }

        // ---- MMA over smem[buf] ----
        #pragma unroll
        for (int kk = 0; kk < 4; kk++) {
            const int kb = kk * 8;
            uint32_t ahi[MTILES][4], alo[MTILES][4];
            #pragma unroll
            for (int i = 0; i < MTILES; i++) {
                int rm = warp_m + i * 16;
                ahi[i][0] = __float_as_uint(As_hi[(rm + g)     * A_STRIDE + kb + t4]);
                ahi[i][1] = __float_as_uint(As_hi[(rm + 8 + g) * A_STRIDE + kb + t4]);
                ahi[i][2] = __float_as_uint(As_hi[(rm + g)     * A_STRIDE + kb + t4 + 4]);
                ahi[i][3] = __float_as_uint(As_hi[(rm + 8 + g) * A_STRIDE + kb + t4 + 4]);
                alo[i][0] = __float_as_uint(As_lo[(rm + g)     * A_STRIDE + kb + t4]);
                alo[i][1] = __float_as_uint(As_lo[(rm + 8 + g) * A_STRIDE + kb + t4]);
                alo[i][2] = __float_as_uint(As_lo[(rm + g)     * A_STRIDE + kb + t4 + 4]);
                alo[i][3] = __float_as_uint(As_lo[(rm + 8 + g) * A_STRIDE + kb + t4 + 4]);
            }
            uint32_t bhi[NTILES][2], blo[NTILES][2];
            #pragma unroll
            for (int j = 0; j < NTILES; j++) {
                int cn = warp_n + j * 8 + g;
                bhi[j][0] = __float_as_uint(Bs_hi[(kb + t4)     * B_STRIDE + cn]);
                bhi[j][1] = __float_as_uint(Bs_hi[(kb + t4 + 4) * B_STRIDE + cn]);
                blo[j][0] = __float_as_uint(Bs_lo[(kb + t4)     * B_STRIDE + cn]);
                blo[j][1] = __float_as_uint(Bs_lo[(kb + t4 + 4) * B_STRIDE + cn]);
            }
            #pragma unroll
            for (int i = 0; i < MTILES; i++)
                #pragma unroll
                for (int j = 0; j < NTILES; j++) {
                    mma_tf32(acc[i][j], ahi[i], bhi[j]);
                    mma_tf32(acc[i][j], ahi[i], blo[j]);
                    mma_tf32(acc[i][j], alo[i], bhi[j]);
                }
        }
    }

    // ---- Epilogue: bias + store (c0,c1 -> row g; c2,c3 -> row g+8) ----
    #pragma unroll
    for (int i = 0; i < MTILES; i++) {
        #pragma unroll
        for (int j = 0; j < NTILES; j++) {
            int col_loc = warp_n + j * 8 + 2 * t4;
            int cng = n0 + col_loc;
            float b0 = bias[cng], b1 = bias[cng + 1];
            int r0 = m0 + warp_m + i * 16 + g;
            int r1 = r0 + 8;
            float2 v0 = make_float2(acc[i][j][0] + b0, acc[i][j][1] + b1);
            float2 v1 = make_float2(acc[i][j][2] + b0, acc[i][j][3] + b1);
            if (HEADSPLIT) {
                int h = blockIdx.y;
                float* d0 = Y + ((size_t)((r0 >> 8) * H_ + h) * L_ + (r0 & 255)) * DK_ + col_loc;
                float* d1 = Y + ((size_t)((r1 >> 8) * H_ + h) * L_ + (r1 & 255)) * DK_ + col_loc;
                *(float2*)d0 = v0;
                *(float2*)d1 = v1;
            } else {
                *(float2*)(Y + (size_t)r0 * D_ + cng) = v0;
                *(float2*)(Y + (size_t)r1 * D_ + cng) = v1;
            }
        }
    }
}

constexpr int gemm_smem_bytes(int mt) {
    return 2 * (2 * mt * A_STRIDE + 2 * 32 * B_STRIDE) * 4;
}

// QKV: grid (8, 8, 3), MT=128, warps 4x2, head-split output
__global__ __launch_bounds__(256) void qkv_mma_kernel(
    const float* __restrict__ q, const float* __restrict__ k, const float* __restrict__ v,
    const float* __restrict__ Wq, const float* __restrict__ bq,
    const float* __restrict__ Wk, const float* __restrict__ bk,
    const float* __restrict__ Wv, const float* __restrict__ bv)
{
    int z = blockIdx.z;
    const float* X    = (z == 0) ? q  : (z == 1 ? k  : v);
    const float* W    = (z == 0) ? Wq : (z == 1 ? Wk : Wv);
    const float* bias = (z == 0) ? bq : (z == 1 ? bk : bv);
    float* out        = (z == 0) ? g_qh : (z == 1 ? g_kh : g_vh);
    gemm3x_core<128, 4, 2, true>(X, W, bias, out);
}

// Output projection: grid (16, 8), MT=64, warps 2x4, flat output
__global__ __launch_bounds__(256) void out_mma_kernel(
    const float* __restrict__ W, const float* __restrict__ bias, float* __restrict__ Y)
{
    gemm3x_core<64, 2, 4, false>(g_ctx, W, bias, Y);
}

// ===========================================================================
// Fused Bahdanau attention (unchanged). One CTA per (b,h,64-row block).
// ===========================================================================
#define ATTN_SMEM_FLOATS (64*68 + 64*68 + 256*64 + 64*260 + 64 + 64)
#define ATTN_SMEM_BYTES  (ATTN_SMEM_FLOATS * 4)

__global__ __launch_bounds__(256) void attn_kernel(
    const int* __restrict__ mask, const float* __restrict__ vp)
{
    extern __shared__ __align__(16) float sm[];
    float* Qs   = sm;
    float* Ks   = Qs + 64 * 68;
    float* Vs   = Ks + 64 * 68;
    float* S    = Vs + 256 * 64;
    float* vps  = S + 64 * 260;
    float* rinv = vps + 64;

    int tid = threadIdx.x;
    int bh = blockIdx.y;
    int b = bh >> 3;
    int h = bh & 7;
    int i0 = blockIdx.x * 64;

    const float* qh  = g_qh + (size_t)(bh * L_ + i0) * DK_;
    const float* khp = g_kh + (size_t)bh * L_ * DK_;
    const float* vhp = g_vh + (size_t)bh * L_ * DK_;

    if (tid < 64) vps[tid] = vp[h * DK_ + tid];

    {
        int i  = tid >> 2;
        int d0 = (tid & 3) * 16;
        #pragma unroll
        for (int u = 0; u < 4; u++) {
            float4 t4 = *(const float4*)&qh[(size_t)i * DK_ + d0 + u * 4];
            Qs[(d0 + u * 4 + 0) * 68 + i] = t4.x;
            Qs[(d0 + u * 4 + 1) * 68 + i] = t4.y;
            Qs[(d0 + u * 4 + 2) * 68 + i] = t4.z;
            Qs[(d0 + u * 4 + 3) * 68 + i] = t4.w;
        }
    }
    {
        const float4* src = (const float4*)vhp;
        float4* dst = (float4*)Vs;
        #pragma unroll
        for (int t = tid; t < (L_ * DK_) / 4; t += 256) dst[t] = src[t];
    }

    int ti = tid & 15;
    int tj = tid >> 4;

    for (int jb = 0; jb < 4; jb++) {
        __syncthreads();
        {
            int j  = tid >> 2;
            int d0 = (tid & 3) * 16;
            const float* kr = khp + (size_t)(jb * 64 + j) * DK_;
            #pragma unroll
            for (int u = 0; u < 4; u++) {
                float4 t4 = *(const float4*)&kr[d0 + u * 4];
                Ks[(d0 + u * 4 + 0) * 68 + j] = t4.x;
                Ks[(d0 + u * 4 + 1) * 68 + j] = t4.y;
                Ks[(d0 + u * 4 + 2) * 68 + j] = t4.z;
                Ks[(d0 + u * 4 + 3) * 68 + j] = t4.w;
            }
        }
        __syncthreads();

        float acc[4][4] = {};
        #pragma unroll 2
        for (int d = 0; d < 64; d++) {
            float w = vps[d];
            float4 qv = *(const float4*)&Qs[d * 68 + ti * 4];
            float4 kv = *(const float4*)&Ks[d * 68 + tj * 4];
            float qa[4] = {qv.x, qv.y, qv.z, qv.w};
            float kb[4] = {kv.x, kv.y, kv.z, kv.w};
            #pragma unroll
            for (int a = 0; a < 4; a++)
                #pragma unroll
                for (int c = 0; c < 4; c++)
                    acc[a][c] += w * tanh_fast(qa[a] + kb[c]);
        }
        #pragma unroll
        for (int a = 0; a < 4; a++)
            #pragma unroll
            for (int c = 0; c < 4; c++)
                S[(ti * 4 + a) * 260 + jb * 64 + tj * 4 + c] = acc[a][c];
    }
    __syncthreads();

    {
        int warp = tid >> 5, lane = tid & 31;
        for (int r = 0; r < 8; r++) {
            int row = warp * 8 + r;
            const int* mrow = mask + ((size_t)b * L_ + i0 + row) * L_;
            float vals[8];
            float mmax = -3.4e38f;
            #pragma unroll
            for (int c8 = 0; c8 < 8; c8++) {
                int c = c8 * 32 + lane;
                float s = S[row * 260 + c];
                if (mrow[c] == 0) s = -1.0e9f;
                vals[c8] = s;
                mmax = fmaxf(mmax, s);
            }
            #pragma unroll
            for (int off = 16; off > 0; off >>= 1)
                mmax = fmaxf(mmax, __shfl_xor_sync(0xFFFFFFFFu, mmax, off));
            float sum = 0.0f;
            #pragma unroll
            for (int c8 = 0; c8 < 8; c8++) {
                float e = __expf(vals[c8] - mmax);
                S[row * 260 + c8 * 32 + lane] = e;
                sum += e;
            }
            #pragma unroll
            for (int off = 16; off > 0; off >>= 1)
                sum += __shfl_xor_sync(0xFFFFFFFFu, sum, off);
            if (lane == 0) rinv[row] = 1.0f / sum;
        }
    }
    __syncthreads();

    {
        int i   = tid >> 2;
        int dk0 = (tid & 3) * 16;
        float o[16] = {};
        #pragma unroll 4
        for (int j = 0; j < L_; j++) {
            float p = S[i * 260 + j];
            const float4* vr = (const float4*)&Vs[j * DK_ + dk0];
            float4 v0 = vr[0], v1 = vr[1], v2 = vr[2], v3 = vr[3];
            o[0]  += p * v0.x; o[1]  += p * v0.y; o[2]  += p * v0.z; o[3]  += p * v0.w;
            o[4]  += p * v1.x; o[5]  += p * v1.y; o[6]  += p * v1.z; o[7]  += p * v1.w;
            o[8]  += p * v2.x; o[9]  += p * v2.y; o[10] += p * v2.z; o[11] += p * v2.w;
            o[12] += p * v3.x; o[13] += p * v3.y; o[14] += p * v3.z; o[15] += p * v3.w;
        }
        float inv = rinv[i];
        float* dst = &g_ctx[((size_t)b * L_ + i0 + i) * D_ + h * DK_ + dk0];
        #pragma unroll
        for (int u = 0; u < 4; u++) {
            float4 r;
            r.x = o[u * 4 + 0] * inv;
            r.y = o[u * 4 + 1] * inv;
            r.z = o[u * 4 + 2] * inv;
            r.w = o[u * 4 + 3] * inv;
            *(float4*)&dst[u * 4] = r;
        }
    }
}

// ===========================================================================
extern "C" void kernel_launch(void* const* d_in, const int* in_sizes, int n_in,
                              void* d_out, int out_size)
{
    const float* q    = (const float*)d_in[0];
    const float* k    = (const float*)d_in[1];
    const float* v    = (const float*)d_in[2];
    const int*   mask = (const int*)  d_in[3];
    const float* Wq   = (const float*)d_in[4];
    const float* bq   = (const float*)d_in[5];
    const float* Wk   = (const float*)d_in[6];
    const float* bk   = (const float*)d_in[7];
    const float* Wv   = (const float*)d_in[8];
    const float* bv   = (const float*)d_in[9];
    const float* vp   = (const float*)d_in[10];
    const float* W0   = (const float*)d_in[11];
    const float* b0   = (const float*)d_in[12];
    float* out = (float*)d_out;

    static bool attr_set = false;
    if (!attr_set) {
        cudaFuncSetAttribute(attn_kernel,
                             cudaFuncAttributeMaxDynamicSharedMemorySize, ATTN_SMEM_BYTES);
        cudaFuncSetAttribute(qkv_mma_kernel,
                             cudaFuncAttributeMaxDynamicSharedMemorySize, gemm_smem_bytes(128));
        cudaFuncSetAttribute(out_mma_kernel,
                             cudaFuncAttributeMaxDynamicSharedMemorySize, gemm_smem_bytes(64));
        attr_set = true;
    }

    qkv_mma_kernel<<<dim3(8, 8, 3), 256, gemm_smem_bytes(128)>>>(
        q, k, v, Wq, bq, Wk, bk, Wv, bv);
    attn_kernel<<<dim3(4, 32), 256, ATTN_SMEM_BYTES>>>(mask, vp);
    out_mma_kernel<<<dim3(16, 8), 256, gemm_smem_bytes(64)>>>(W0, b0, out);
}